// round 13
// baseline (speedup 1.0000x reference)
#include <cuda_runtime.h>
#include <cuda_fp16.h>
#include <cstdint>
#include <cfloat>

#define BROWS 8192
#define DIM   2048
#define NBLK  (BROWS/128)

#define BM 128
#define BN 128
#define BK 64
#define NCH (DIM/BK)              // 32 k-iterations
#define T_STRIDE 144
#define T_SM_BYTES (128*T_STRIDE)       // 18432
#define A_SM_BYTES T_SM_BYTES
#define STAGE_BYTES (2*T_SM_BYTES)      // 36864
#define NSTAGE 3
#define SMEM_TOTAL (NSTAGE*STAGE_BYTES) // 110592

#define NTHREADS 256              // 8 warps, 2x4 grid of 64x32 warp tiles

#define W_ITEMS 16                // per-layer W transpose items (128 n-cols each)
#define X_ITEMS 64                // convx items (128 rows each)
#define TPL 1024                  // tiles per layer (64 bm x 16 bn)
// ticket layout: [W0(16), X(64)] L0(1024) [W1(16) L1(1024)] [W2] L2 [W3] L3
#define PRE_ITEMS (W_ITEMS + X_ITEMS)                    // 80
#define SEG (W_ITEMS + TPL)                              // 1040
#define TOTAL_TICKETS (PRE_ITEMS + TPL + 3*SEG)          // 4224

// ------------------------- persistent device scratch -------------------------
__device__ __align__(16) __half g_X [(size_t)BROWS * DIM];     // fp16 x
__device__ __align__(16) __half g_Wt[(size_t)4 * DIM * DIM];   // fp16 W^T: [l][n][k]
__device__ __align__(16) __half g_H0[(size_t)BROWS * DIM];
__device__ __align__(16) __half g_H1[(size_t)BROWS * DIM];
__device__ __align__(16) __half g_H2[(size_t)BROWS * DIM];
__device__ int g_route[BROWS];
__device__ int g_ticket;
__device__ int g_done[4][NBLK];   // per-layer per-row-block tile completion
__device__ int g_prepW[4];        // W transpose completion per layer
__device__ int g_prepX;           // convx completion

// ------------------------------- helpers --------------------------------
__device__ __forceinline__ uint32_t smem_u32(const void* p) {
    uint32_t a;
    asm("{ .reg .u64 t; cvta.to.shared.u64 t, %1; cvt.u32.u64 %0, t; }" : "=r"(a) : "l"(p));
    return a;
}
#define CP_ASYNC16(dst, src) \
    asm volatile("cp.async.cg.shared.global [%0], [%1], 16;" :: "r"(dst), "l"(src) : "memory")
#define LDSM_X4(r0, r1, r2, r3, addr) \
    asm volatile("ldmatrix.sync.aligned.m8n8.x4.shared.b16 {%0,%1,%2,%3}, [%4];" \
                 : "=r"(r0), "=r"(r1), "=r"(r2), "=r"(r3) : "r"(addr))

__device__ __forceinline__ float gelu_f(float x) {
    float x3 = x * x * x;
    float t = tanhf(0.7978845608028654f * (x + 0.044715f * x3));
    return 0.5f * x * (1.f + t);
}

// ---------------------------------------------------------------------------
// Fused: min/max + router MLP + scheduler-state reset. One block, 1024 thr.
// ---------------------------------------------------------------------------
__global__ __launch_bounds__(1024)
void route_fused_kernel(const float* __restrict__ unc,
                        const float* __restrict__ rw1, const float* __restrict__ rb1,
                        const float* __restrict__ rw2, const float* __restrict__ rb2,
                        const float* __restrict__ rw3, const float* __restrict__ rb3,
                        float* __restrict__ out_mask) {
    __shared__ float smin[1024], smax[1024];
    __shared__ float s_w1[32], s_b1[32], s_w2[512], s_b2[16], s_w3[48], s_b3[3];
    __shared__ float s_mn, s_mx;
    int t = threadIdx.x;

    if (t < 32) { s_w1[t] = rw1[t]; s_b1[t] = rb1[t]; }
    if (t >= 256 && t < 768) s_w2[t - 256] = rw2[t - 256];
    if (t >= 768 && t < 784) s_b2[t - 768] = rb2[t - 768];
    if (t >= 800 && t < 848) s_w3[t - 800] = rw3[t - 800];
    if (t >= 864 && t < 867) s_b3[t - 864] = rb3[t - 864];
    // reset persistent-scheduler state (graph-replay safe)
    if (t < 4 * NBLK) ((int*)g_done)[t] = 0;
    if (t >= 512 && t < 516) g_prepW[t - 512] = 0;
    if (t == 516) g_prepX = 0;
    if (t == 517) g_ticket = 0;

    float mn = FLT_MAX, mx = -FLT_MAX;
    for (int i = t; i < BROWS; i += 1024) {
        float v = unc[i];
        mn = fminf(mn, v); mx = fmaxf(mx, v);
    }
    smin[t] = mn; smax[t] = mx;
    __syncthreads();
    for (int s = 512; s > 0; s >>= 1) {
        if (t < s) {
            smin[t] = fminf(smin[t], smin[t + s]);
            smax[t] = fmaxf(smax[t], smax[t + s]);
        }
        __syncthreads();
    }
    if (t == 0) { s_mn = smin[0]; s_mx = smax[0]; }
    __syncthreads();

    float vmn = s_mn, vmx = s_mx;
    for (int i = t; i < BROWS; i += 1024) {
        float u = (unc[i] - vmn) / (vmx - vmn + 1e-8f);
        float h1[32];
#pragma unroll
        for (int j = 0; j < 32; j++) h1[j] = fmaxf(fmaf(u, s_w1[j], s_b1[j]), 0.f);
        float h2[16];
#pragma unroll
        for (int j = 0; j < 16; j++) {
            float a = s_b2[j];
#pragma unroll
            for (int k = 0; k < 32; k++) a = fmaf(h1[k], s_w2[k * 16 + j], a);
            h2[j] = fmaxf(a, 0.f);
        }
        float l[3];
#pragma unroll
        for (int j = 0; j < 3; j++) {
            float a = s_b3[j];
#pragma unroll
            for (int k = 0; k < 16; k++) a = fmaf(h2[k], s_w3[k * 3 + j], a);
            l[j] = a;
        }
        int r = 0; float best = l[0];
        if (l[1] > best) { best = l[1]; r = 1; }
        if (l[2] > best) { best = l[2]; r = 2; }
        g_route[i]  = r;
        out_mask[i] = (float)r;
    }
}

// ---------------------------------------------------------------------------
// prep items (run inside the persistent kernel, 256 threads each)
// ---------------------------------------------------------------------------
__device__ void convx_item(const float* __restrict__ x, int ib) {
    const float* src = x + (size_t)ib * 128 * DIM;
    __half* dst = g_X + (size_t)ib * 128 * DIM;
    int tid = threadIdx.x;
#pragma unroll 4
    for (int it = 0; it < 128; it++) {
        size_t off = (size_t)(tid + it * 256) * 8;
        float4 v0 = *(const float4*)(src + off);
        float4 v1 = *(const float4*)(src + off + 4);
        uint4 o;
        __half2* ho = (__half2*)&o;
        ho[0] = __floats2half2_rn(v0.x, v0.y);
        ho[1] = __floats2half2_rn(v0.z, v0.w);
        ho[2] = __floats2half2_rn(v1.x, v1.y);
        ho[3] = __floats2half2_rn(v1.z, v1.w);
        *(uint4*)(dst + off) = o;
    }
}

// transpose 128 n-cols (block nb) of W[l][k][n] -> g_Wt[l][n][k], fp16
__device__ void transW_item(const float* __restrict__ Ws, int l, int nb, char* smem) {
    float* s = (float*)smem;            // tile [32][132]
    const float* Wl = Ws + (size_t)l * DIM * DIM;
    __half* Wt = g_Wt + (size_t)l * DIM * DIM;
    int n0 = nb * 128;
    int tid = threadIdx.x;
    int r  = tid >> 1;                  // n-row within block 0..127
    int kh = (tid & 1) * 16;            // k half 0/16
    for (int k0 = 0; k0 < DIM; k0 += 32) {
        __syncthreads();
#pragma unroll
        for (int it = 0; it < 4; it++) {
            int g = tid + it * 256;
            int kk = g >> 5;
            int n4 = (g & 31) * 4;
            float4 v = *(const float4*)(Wl + (size_t)(k0 + kk) * DIM + n0 + n4);
            *(float4*)(s + kk * 132 + n4) = v;
        }
        __syncthreads();
        __half h[16];
#pragma unroll
        for (int kk = 0; kk < 16; kk++)
            h[kk] = __float2half_rn(s[(kh + kk) * 132 + r]);
        // 16 halves = 32 bytes = TWO uint4 stores (R12 bug: only one was stored)
        *(uint4*)(Wt + (size_t)(n0 + r) * DIM + k0 + kh)     = ((uint4*)h)[0];
        *(uint4*)(Wt + (size_t)(n0 + r) * DIM + k0 + kh + 8) = ((uint4*)h)[1];
    }
}

// ---------------------------------------------------------------------------
// Persistent kernel: prep items + all 4 GEMM layers, ticket scheduler.
// GEMM tile config identical to R11: 128x128x64, 8 warps 64x32, 3-stage, 2 CTA/SM.
// ---------------------------------------------------------------------------
__global__ __launch_bounds__(NTHREADS, 2)
void gemm_persistent(const float* __restrict__ x, const float* __restrict__ Ws,
                     const float* __restrict__ ball, float* __restrict__ outp) {
    extern __shared__ char smem[];
    __shared__ int s_item;
    uint32_t smem_base = smem_u32(smem);

    int tid  = threadIdx.x;
    int warp = tid >> 5, lane = tid & 31;
    int wm = warp >> 2, wn = warp & 3;
    int gq = lane >> 2, tr = lane & 3;

    int a_row  = ((lane >> 3) & 1) * 8 + (lane & 7);
    int a_colB = (lane >> 4) * 16;
    int b_row  = (lane >> 4) * 8 + (lane & 7);
    int b_colB = ((lane >> 3) & 1) * 16;

    for (;;) {
        if (tid == 0) s_item = atomicAdd(&g_ticket, 1);
        __syncthreads();
        int item = s_item;
        if (item >= TOTAL_TICKETS) return;

        // ---------------- prep tickets ----------------
        if (item < PRE_ITEMS) {
            if (item < W_ITEMS) {
                transW_item(Ws, 0, item, smem);
                __threadfence(); __syncthreads();
                if (tid == 0) atomicAdd(&g_prepW[0], 1);
            } else {
                convx_item(x, item - W_ITEMS);
                __threadfence(); __syncthreads();
                if (tid == 0) atomicAdd(&g_prepX, 1);
            }
            continue;
        }
        int rem = item - PRE_ITEMS;
        int layer, tile;
        if (rem < TPL) { layer = 0; tile = rem; }
        else {
            int b = (rem - TPL) / SEG;
            int r = (rem - TPL) % SEG;
            layer = b + 1;
            if (r < W_ITEMS) {
                transW_item(Ws, layer, r, smem);
                __threadfence(); __syncthreads();
                if (tid == 0) atomicAdd(&g_prepW[layer], 1);
                continue;
            }
            tile = r - W_ITEMS;
        }
        int bm = tile >> 4, bn = tile & 15;

        const __half* A; __half* Hptr; int outLevel;
        switch (layer) {
            case 0:  A = g_X;  Hptr = g_H0;    outLevel = 0;  break;
            case 1:  A = g_H0; Hptr = g_H1;    outLevel = 1;  break;
            case 2:  A = g_H1; Hptr = g_H2;    outLevel = -1; break;
            default: A = g_H2; Hptr = nullptr; outLevel = 2;  break;
        }
        const float* bias = ball + layer * DIM;
        const char* aSrc = (const char*)(A + (size_t)bm * BM * DIM);
        const char* bSrc = (const char*)(g_Wt + (size_t)layer * DIM * DIM + (size_t)bn * BN * DIM);

        // dependencies: prev layer row-block done + this layer's W transposed (+X for L0)
        if (tid == 0) {
            if (layer == 0) {
                while (*(volatile int*)&g_prepX < X_ITEMS ||
                       *(volatile int*)&g_prepW[0] < W_ITEMS) __nanosleep(64);
            } else {
                while (*(volatile int*)&g_done[layer - 1][bm] < 16 ||
                       *(volatile int*)&g_prepW[layer] < W_ITEMS) __nanosleep(64);
            }
            __threadfence();
        }
        __syncthreads();

        float acc[4][4][4];
#pragma unroll
        for (int i = 0; i < 4; i++)
#pragma unroll
            for (int j = 0; j < 4; j++)
#pragma unroll
                for (int r = 0; r < 4; r++) acc[i][j][r] = 0.f;

        auto issue = [&](int c) {
            int slot = c % NSTAGE;
            uint32_t ab = smem_base + slot * STAGE_BYTES;
            uint32_t bb = ab + A_SM_BYTES;
            #pragma unroll
            for (int i = 0; i < 4; i++) {
                int g = tid + i * NTHREADS;
                int r = g >> 3, gc = g & 7;
                CP_ASYNC16(ab + (uint32_t)(r * T_STRIDE + gc * 16),
                           aSrc + (size_t)r * (DIM * 2) + (size_t)c * (BK * 2) + gc * 16);
            }
            #pragma unroll
            for (int i = 0; i < 4; i++) {
                int g = tid + i * NTHREADS;
                int r = g >> 3, gc = g & 7;
                CP_ASYNC16(bb + (uint32_t)(r * T_STRIDE + gc * 16),
                           bSrc + (size_t)r * (DIM * 2) + (size_t)c * (BK * 2) + gc * 16);
            }
            asm volatile("cp.async.commit_group;" ::: "memory");
        };

        issue(0);
        issue(1);

        for (int c = 0; c < NCH; c++) {
            if (c < NCH - 1) asm volatile("cp.async.wait_group 1;" ::: "memory");
            else             asm volatile("cp.async.wait_group 0;" ::: "memory");
            __syncthreads();
            if (c + 2 < NCH) issue(c + 2);

            int slot = c % NSTAGE;
            uint32_t aBase = smem_base + slot * STAGE_BYTES
                           + (uint32_t)((wm * 64 + a_row) * T_STRIDE + a_colB);
            uint32_t bBase = smem_base + slot * STAGE_BYTES + A_SM_BYTES
                           + (uint32_t)((wn * 32 + b_row) * T_STRIDE + b_colB);

#pragma unroll
            for (int ks = 0; ks < 4; ks++) {
                uint32_t af[4][4], bf[4][2];
#pragma unroll
                for (int i = 0; i < 4; i++)
                    LDSM_X4(af[i][0], af[i][1], af[i][2], af[i][3],
                            aBase + (uint32_t)(i * 16 * T_STRIDE + ks * 32));
#pragma unroll
                for (int jp = 0; jp < 2; jp++)
                    LDSM_X4(bf[2 * jp][0], bf[2 * jp][1], bf[2 * jp + 1][0], bf[2 * jp + 1][1],
                            bBase + (uint32_t)(jp * 16 * T_STRIDE + ks * 32));
#pragma unroll
                for (int i = 0; i < 4; i++)
#pragma unroll
                    for (int j = 0; j < 4; j++) {
                        asm volatile(
                            "mma.sync.aligned.m16n8k16.row.col.f32.f16.f16.f32 "
                            "{%0,%1,%2,%3}, {%4,%5,%6,%7}, {%8,%9}, {%0,%1,%2,%3};"
                            : "+f"(acc[i][j][0]), "+f"(acc[i][j][1]),
                              "+f"(acc[i][j][2]), "+f"(acc[i][j][3])
                            : "r"(af[i][0]), "r"(af[i][1]), "r"(af[i][2]), "r"(af[i][3]),
                              "r"(bf[j][0]), "r"(bf[j][1]));
                    }
            }
        }

        // ---- epilogue: bias + GELU; H fp16, routed rows -> out (fp32) ----
        int rbase = bm * BM + wm * 64;
        int cbase = bn * BN + wn * 32;
#pragma unroll
        for (int i = 0; i < 4; i++) {
            int row0 = rbase + i * 16 + gq;
            int row1 = row0 + 8;
            int rt0 = g_route[row0], rt1 = g_route[row1];
#pragma unroll
            for (int j = 0; j < 4; j++) {
                int col = cbase + j * 8 + 2 * tr;
                float2 bb = *(const float2*)(bias + col);
                float v00 = gelu_f(acc[i][j][0] + bb.x);
                float v01 = gelu_f(acc[i][j][1] + bb.y);
                float v10 = gelu_f(acc[i][j][2] + bb.x);
                float v11 = gelu_f(acc[i][j][3] + bb.y);
                if (Hptr) {
                    *(__half2*)&Hptr[(size_t)row0 * DIM + col] = __floats2half2_rn(v00, v01);
                    *(__half2*)&Hptr[(size_t)row1 * DIM + col] = __floats2half2_rn(v10, v11);
                }
                if (outLevel >= 0) {
                    if (rt0 == outLevel) *(float2*)&outp[(size_t)row0 * DIM + col] = make_float2(v00, v01);
                    if (rt1 == outLevel) *(float2*)&outp[(size_t)row1 * DIM + col] = make_float2(v10, v11);
                }
            }
        }

        __threadfence();
        __syncthreads();
        if (tid == 0 && layer < 3) atomicAdd(&g_done[layer][bm], 1);
    }
}

// ---------------------------------------------------------------------------
extern "C" void kernel_launch(void* const* d_in, const int* in_sizes, int n_in,
                              void* d_out, int out_size) {
    const float* x   = (const float*)d_in[0];
    const float* unc = (const float*)d_in[1];
    const float* Ws  = (const float*)d_in[2];
    const float* bs  = (const float*)d_in[3];
    const float* rw1 = (const float*)d_in[4];
    const float* rb1 = (const float*)d_in[5];
    const float* rw2 = (const float*)d_in[6];
    const float* rb2 = (const float*)d_in[7];
    const float* rw3 = (const float*)d_in[8];
    const float* rb3 = (const float*)d_in[9];

    float* out  = (float*)d_out;
    float* mask = out + (size_t)BROWS * DIM;

    cudaFuncSetAttribute(gemm_persistent, cudaFuncAttributeMaxDynamicSharedMemorySize, SMEM_TOTAL);

    int sms = 148;
    cudaDeviceGetAttribute(&sms, cudaDevAttrMultiProcessorCount, 0);

    route_fused_kernel<<<1, 1024>>>(unc, rw1, rb1, rw2, rb2, rw3, rb3, mask);
    gemm_persistent<<<2 * sms, NTHREADS, SMEM_TOTAL>>>(x, Ws, bs, out);
}

// round 14
// speedup vs baseline: 1.1159x; 1.1159x over previous
#include <cuda_runtime.h>
#include <cuda_fp16.h>
#include <cstdint>
#include <cfloat>

#define BROWS 8192
#define DIM   2048
#define NBLK  (BROWS/128)

#define BM 128
#define BN 128
#define BK 64
#define NCH (DIM/BK)              // 32 k-iterations
#define A_STRIDE 144              // A tile row: 64 fp16 =128B, pad to 144B
#define B_STRIDE 272              // B tile row: 128 fp16 =256B, pad to 272B
#define A_SM_BYTES (128*A_STRIDE)       // 18432
#define B_SM_BYTES (64*B_STRIDE)        // 17408
#define STAGE_BYTES (A_SM_BYTES + B_SM_BYTES)  // 35840
#define NSTAGE 3
#define SMEM_TOTAL (NSTAGE*STAGE_BYTES) // 107520

#define NTHREADS 256              // 8 warps, 2x4 grid of 64x32 warp tiles

#define W_ITEMS 16                // per-layer elementwise W fp16-convert items
#define TPL 1024                  // tiles per layer (64 bm x 16 bn)
#define SEG (W_ITEMS + TPL)       // 1040
#define TOTAL_TICKETS (4*SEG)     // 4160

// ------------------------- persistent device scratch -------------------------
__device__ __align__(16) __half g_X [(size_t)BROWS * DIM];     // fp16 x
__device__ __align__(16) __half g_Wh[(size_t)4 * DIM * DIM];   // fp16 W, native [l][k][n]
__device__ __align__(16) __half g_H0[(size_t)BROWS * DIM];
__device__ __align__(16) __half g_H1[(size_t)BROWS * DIM];
__device__ __align__(16) __half g_H2[(size_t)BROWS * DIM];
__device__ int g_route[BROWS];
__device__ int g_ticket;
__device__ int g_done[4][NBLK];   // per-layer per-row-block tile completion
__device__ int g_prepW[4];        // W convert completion per layer

// ------------------------------- helpers --------------------------------
__device__ __forceinline__ uint32_t smem_u32(const void* p) {
    uint32_t a;
    asm("{ .reg .u64 t; cvta.to.shared.u64 t, %1; cvt.u32.u64 %0, t; }" : "=r"(a) : "l"(p));
    return a;
}
#define CP_ASYNC16(dst, src) \
    asm volatile("cp.async.cg.shared.global [%0], [%1], 16;" :: "r"(dst), "l"(src) : "memory")
#define LDSM_X4(r0, r1, r2, r3, addr) \
    asm volatile("ldmatrix.sync.aligned.m8n8.x4.shared.b16 {%0,%1,%2,%3}, [%4];" \
                 : "=r"(r0), "=r"(r1), "=r"(r2), "=r"(r3) : "r"(addr))
#define LDSM_X4_T(r0, r1, r2, r3, addr) \
    asm volatile("ldmatrix.sync.aligned.m8n8.x4.trans.shared.b16 {%0,%1,%2,%3}, [%4];" \
                 : "=r"(r0), "=r"(r1), "=r"(r2), "=r"(r3) : "r"(addr))

__device__ __forceinline__ float gelu_f(float x) {
    float x3 = x * x * x;
    float t = tanhf(0.7978845608028654f * (x + 0.044715f * x3));
    return 0.5f * x * (1.f + t);
}

// ---------------------------------------------------------------------------
// Fused: min/max + router MLP + scheduler-state reset. One block, 1024 thr.
// ---------------------------------------------------------------------------
__global__ __launch_bounds__(1024)
void route_fused_kernel(const float* __restrict__ unc,
                        const float* __restrict__ rw1, const float* __restrict__ rb1,
                        const float* __restrict__ rw2, const float* __restrict__ rb2,
                        const float* __restrict__ rw3, const float* __restrict__ rb3,
                        float* __restrict__ out_mask) {
    __shared__ float smin[1024], smax[1024];
    __shared__ float s_w1[32], s_b1[32], s_w2[512], s_b2[16], s_w3[48], s_b3[3];
    __shared__ float s_mn, s_mx;
    int t = threadIdx.x;

    if (t < 32) { s_w1[t] = rw1[t]; s_b1[t] = rb1[t]; }
    if (t >= 256 && t < 768) s_w2[t - 256] = rw2[t - 256];
    if (t >= 768 && t < 784) s_b2[t - 768] = rb2[t - 768];
    if (t >= 800 && t < 848) s_w3[t - 800] = rw3[t - 800];
    if (t >= 864 && t < 867) s_b3[t - 864] = rb3[t - 864];
    // reset persistent-scheduler state (graph-replay safe)
    if (t < 4 * NBLK) ((int*)g_done)[t] = 0;
    if (t >= 512 && t < 516) g_prepW[t - 512] = 0;
    if (t == 516) g_ticket = 0;

    float mn = FLT_MAX, mx = -FLT_MAX;
    for (int i = t; i < BROWS; i += 1024) {
        float v = unc[i];
        mn = fminf(mn, v); mx = fmaxf(mx, v);
    }
    smin[t] = mn; smax[t] = mx;
    __syncthreads();
    for (int s = 512; s > 0; s >>= 1) {
        if (t < s) {
            smin[t] = fminf(smin[t], smin[t + s]);
            smax[t] = fmaxf(smax[t], smax[t + s]);
        }
        __syncthreads();
    }
    if (t == 0) { s_mn = smin[0]; s_mx = smax[0]; }
    __syncthreads();

    float vmn = s_mn, vmx = s_mx;
    for (int i = t; i < BROWS; i += 1024) {
        float u = (unc[i] - vmn) / (vmx - vmn + 1e-8f);
        float h1[32];
#pragma unroll
        for (int j = 0; j < 32; j++) h1[j] = fmaxf(fmaf(u, s_w1[j], s_b1[j]), 0.f);
        float h2[16];
#pragma unroll
        for (int j = 0; j < 16; j++) {
            float a = s_b2[j];
#pragma unroll
            for (int k = 0; k < 32; k++) a = fmaf(h1[k], s_w2[k * 16 + j], a);
            h2[j] = fmaxf(a, 0.f);
        }
        float l[3];
#pragma unroll
        for (int j = 0; j < 3; j++) {
            float a = s_b3[j];
#pragma unroll
            for (int k = 0; k < 16; k++) a = fmaf(h2[k], s_w3[k * 3 + j], a);
            l[j] = a;
        }
        int r = 0; float best = l[0];
        if (l[1] > best) { best = l[1]; r = 1; }
        if (l[2] > best) { best = l[2]; r = 2; }
        g_route[i]  = r;
        out_mask[i] = (float)r;
    }
}

// ---------------------------------------------------------------------------
// convx: x -> g_X (fp16), standalone coalesced kernel
// ---------------------------------------------------------------------------
__global__ void convx_kernel(const float* __restrict__ x) {
    size_t i = ((size_t)blockIdx.x * 256 + threadIdx.x) * 8;
    float4 v0 = *(const float4*)(x + i);
    float4 v1 = *(const float4*)(x + i + 4);
    uint4 o;
    __half2* ho = (__half2*)&o;
    ho[0] = __floats2half2_rn(v0.x, v0.y);
    ho[1] = __floats2half2_rn(v0.z, v0.w);
    ho[2] = __floats2half2_rn(v1.x, v1.y);
    ho[3] = __floats2half2_rn(v1.z, v1.w);
    *(uint4*)(g_X + i) = o;
}

// elementwise W fp32->fp16 convert item (128 k-rows of layer l), coalesced
__device__ void convw_item(const float* __restrict__ Ws, int l, int ib) {
    const float* src = Ws + (size_t)l * DIM * DIM + (size_t)ib * 128 * DIM;
    __half* dst = g_Wh + (size_t)l * DIM * DIM + (size_t)ib * 128 * DIM;
    int tid = threadIdx.x;
#pragma unroll 4
    for (int it = 0; it < 128; it++) {
        size_t off = (size_t)(tid + it * 256) * 8;
        float4 v0 = *(const float4*)(src + off);
        float4 v1 = *(const float4*)(src + off + 4);
        uint4 o;
        __half2* ho = (__half2*)&o;
        ho[0] = __floats2half2_rn(v0.x, v0.y);
        ho[1] = __floats2half2_rn(v0.z, v0.w);
        ho[2] = __floats2half2_rn(v1.x, v1.y);
        ho[3] = __floats2half2_rn(v1.z, v1.w);
        *(uint4*)(dst + off) = o;
    }
}

// ---------------------------------------------------------------------------
// Persistent kernel: W-convert items + all 4 GEMM layers, ticket scheduler.
// GEMM: 128x128x64, 8 warps 64x32, 3-stage cp.async, 2 CTA/SM.
// B tiles loaded from native [k][n] W via ldmatrix.trans (no transpose prep).
// ---------------------------------------------------------------------------
__global__ __launch_bounds__(NTHREADS, 2)
void gemm_persistent(const float* __restrict__ x, const float* __restrict__ Ws,
                     const float* __restrict__ ball, float* __restrict__ outp) {
    extern __shared__ char smem[];
    __shared__ int s_item;
    uint32_t smem_base = smem_u32(smem);

    int tid  = threadIdx.x;
    int warp = tid >> 5, lane = tid & 31;
    int wm = warp >> 2, wn = warp & 3;
    int gq = lane >> 2, tr = lane & 3;

    // A ldmatrix lane addressing (non-trans, K-major rows)
    int a_row  = ((lane >> 3) & 1) * 8 + (lane & 7);
    int a_colB = (lane >> 4) * 16;
    // B ldmatrix.trans lane addressing ([k][n] rows)
    int b_row  = lane & 15;               // k within k16
    int b_colB = (lane >> 4) * 16;        // n8 block within n16 (8 fp16 = 16B)

    for (;;) {
        if (tid == 0) s_item = atomicAdd(&g_ticket, 1);
        __syncthreads();
        int item = s_item;
        if (item >= TOTAL_TICKETS) return;

        int layer = item / SEG;
        int r     = item % SEG;
        if (r < W_ITEMS) {
            convw_item(Ws, layer, r);
            __threadfence(); __syncthreads();
            if (tid == 0) atomicAdd(&g_prepW[layer], 1);
            continue;
        }
        int tile = r - W_ITEMS;
        int bm = tile >> 4, bn = tile & 15;

        const __half* A; __half* Hptr; int outLevel;
        switch (layer) {
            case 0:  A = g_X;  Hptr = g_H0;    outLevel = 0;  break;
            case 1:  A = g_H0; Hptr = g_H1;    outLevel = 1;  break;
            case 2:  A = g_H1; Hptr = g_H2;    outLevel = -1; break;
            default: A = g_H2; Hptr = nullptr; outLevel = 2;  break;
        }
        const float* bias = ball + layer * DIM;
        const char* aSrc = (const char*)(A + (size_t)bm * BM * DIM);
        // B tile: native [k][n]; tile origin = column bn*BN
        const char* bSrc = (const char*)(g_Wh + (size_t)layer * DIM * DIM + (size_t)bn * BN);

        // dependencies: this layer's W converted; prev layer row-block done
        if (tid == 0) {
            if (layer == 0) {
                while (*(volatile int*)&g_prepW[0] < W_ITEMS) __nanosleep(64);
            } else {
                while (*(volatile int*)&g_done[layer - 1][bm] < 16 ||
                       *(volatile int*)&g_prepW[layer] < W_ITEMS) __nanosleep(64);
            }
            __threadfence();
        }
        __syncthreads();

        float acc[4][4][4];
#pragma unroll
        for (int i = 0; i < 4; i++)
#pragma unroll
            for (int j = 0; j < 4; j++)
#pragma unroll
                for (int q = 0; q < 4; q++) acc[i][j][q] = 0.f;

        auto issue = [&](int c) {
            int slot = c % NSTAGE;
            uint32_t ab = smem_base + slot * STAGE_BYTES;
            uint32_t bb = ab + A_SM_BYTES;
            // A: 128 rows x 8 granules @144B stride
            #pragma unroll
            for (int i = 0; i < 4; i++) {
                int g = tid + i * NTHREADS;
                int rr = g >> 3, gc = g & 7;
                CP_ASYNC16(ab + (uint32_t)(rr * A_STRIDE + gc * 16),
                           aSrc + (size_t)rr * (DIM * 2) + (size_t)c * (BK * 2) + gc * 16);
            }
            // B: 64 k-rows x 16 granules @272B stride  (row = k, 256B of n data)
            #pragma unroll
            for (int i = 0; i < 4; i++) {
                int g = tid + i * NTHREADS;
                int rr = g >> 4, gc = g & 15;
                CP_ASYNC16(bb + (uint32_t)(rr * B_STRIDE + gc * 16),
                           bSrc + (size_t)(c * BK + rr) * (DIM * 2) + gc * 16);
            }
            asm volatile("cp.async.commit_group;" ::: "memory");
        };

        issue(0);
        issue(1);

        for (int c = 0; c < NCH; c++) {
            if (c < NCH - 1) asm volatile("cp.async.wait_group 1;" ::: "memory");
            else             asm volatile("cp.async.wait_group 0;" ::: "memory");
            __syncthreads();
            if (c + 2 < NCH) issue(c + 2);

            int slot = c % NSTAGE;
            uint32_t aBase = smem_base + slot * STAGE_BYTES
                           + (uint32_t)((wm * 64 + a_row) * A_STRIDE + a_colB);
            uint32_t bBase = smem_base + slot * STAGE_BYTES + A_SM_BYTES
                           + (uint32_t)(b_row * B_STRIDE + wn * 64 + b_colB);

#pragma unroll
            for (int ks = 0; ks < 4; ks++) {
                uint32_t af[4][4], bf[4][2];
#pragma unroll
                for (int i = 0; i < 4; i++)
                    LDSM_X4(af[i][0], af[i][1], af[i][2], af[i][3],
                            aBase + (uint32_t)(i * 16 * A_STRIDE + ks * 32));
#pragma unroll
                for (int jp = 0; jp < 2; jp++)
                    LDSM_X4_T(bf[2 * jp][0], bf[2 * jp][1], bf[2 * jp + 1][0], bf[2 * jp + 1][1],
                              bBase + (uint32_t)(ks * 16 * B_STRIDE + jp * 32));
#pragma unroll
                for (int i = 0; i < 4; i++)
#pragma unroll
                    for (int j = 0; j < 4; j++) {
                        asm volatile(
                            "mma.sync.aligned.m16n8k16.row.col.f32.f16.f16.f32 "
                            "{%0,%1,%2,%3}, {%4,%5,%6,%7}, {%8,%9}, {%0,%1,%2,%3};"
                            : "+f"(acc[i][j][0]), "+f"(acc[i][j][1]),
                              "+f"(acc[i][j][2]), "+f"(acc[i][j][3])
                            : "r"(af[i][0]), "r"(af[i][1]), "r"(af[i][2]), "r"(af[i][3]),
                              "r"(bf[j][0]), "r"(bf[j][1]));
                    }
            }
        }

        // ---- epilogue: bias + GELU; H fp16, routed rows -> out (fp32) ----
        int rbase = bm * BM + wm * 64;
        int cbase = bn * BN + wn * 32;
#pragma unroll
        for (int i = 0; i < 4; i++) {
            int row0 = rbase + i * 16 + gq;
            int row1 = row0 + 8;
            int rt0 = g_route[row0], rt1 = g_route[row1];
#pragma unroll
            for (int j = 0; j < 4; j++) {
                int col = cbase + j * 8 + 2 * tr;
                float2 bb = *(const float2*)(bias + col);
                float v00 = gelu_f(acc[i][j][0] + bb.x);
                float v01 = gelu_f(acc[i][j][1] + bb.y);
                float v10 = gelu_f(acc[i][j][2] + bb.x);
                float v11 = gelu_f(acc[i][j][3] + bb.y);
                if (Hptr) {
                    *(__half2*)&Hptr[(size_t)row0 * DIM + col] = __floats2half2_rn(v00, v01);
                    *(__half2*)&Hptr[(size_t)row1 * DIM + col] = __floats2half2_rn(v10, v11);
                }
                if (outLevel >= 0) {
                    if (rt0 == outLevel) *(float2*)&outp[(size_t)row0 * DIM + col] = make_float2(v00, v01);
                    if (rt1 == outLevel) *(float2*)&outp[(size_t)row1 * DIM + col] = make_float2(v10, v11);
                }
            }
        }

        __threadfence();
        __syncthreads();
        if (tid == 0 && layer < 3) atomicAdd(&g_done[layer][bm], 1);
    }
}

// ---------------------------------------------------------------------------
extern "C" void kernel_launch(void* const* d_in, const int* in_sizes, int n_in,
                              void* d_out, int out_size) {
    const float* x   = (const float*)d_in[0];
    const float* unc = (const float*)d_in[1];
    const float* Ws  = (const float*)d_in[2];
    const float* bs  = (const float*)d_in[3];
    const float* rw1 = (const float*)d_in[4];
    const float* rb1 = (const float*)d_in[5];
    const float* rw2 = (const float*)d_in[6];
    const float* rb2 = (const float*)d_in[7];
    const float* rw3 = (const float*)d_in[8];
    const float* rb3 = (const float*)d_in[9];

    float* out  = (float*)d_out;
    float* mask = out + (size_t)BROWS * DIM;

    cudaFuncSetAttribute(gemm_persistent, cudaFuncAttributeMaxDynamicSharedMemorySize, SMEM_TOTAL);

    int sms = 148;
    cudaDeviceGetAttribute(&sms, cudaDevAttrMultiProcessorCount, 0);

    route_fused_kernel<<<1, 1024>>>(unc, rw1, rb1, rw2, rb2, rw3, rb3, mask);
    convx_kernel<<<(BROWS * DIM) / (256 * 8), 256>>>(x);
    gemm_persistent<<<2 * sms, NTHREADS, SMEM_TOTAL>>>(x, Ws, bs, out);
}

// round 15
// speedup vs baseline: 1.3969x; 1.2518x over previous
#include <cuda_runtime.h>
#include <cuda_fp16.h>
#include <cstdint>
#include <cfloat>

#define BROWS 8192
#define DIM   2048
#define NBLK  (BROWS/128)

#define BM 128
#define BN 128
#define BK 64
#define NCH (DIM/BK)              // 32 k-iterations
#define T_STRIDE 144
#define T_SM_BYTES (128*T_STRIDE)       // 18432
#define A_SM_BYTES T_SM_BYTES
#define STAGE_BYTES (2*T_SM_BYTES)      // 36864
#define NSTAGE 3
#define SMEM_TOTAL (NSTAGE*STAGE_BYTES) // 110592

#define NTHREADS 256              // 8 warps, 2x4 grid of 64x32 warp tiles

#define TPL 1024                  // tiles per layer (64 bm x 16 bn)
#define TOTAL_TILES (4*TPL)

// ------------------------- persistent device scratch -------------------------
__device__ __align__(16) __half g_X [(size_t)BROWS * DIM];     // fp16 x
__device__ __align__(16) __half g_Wt[(size_t)4 * DIM * DIM];   // fp16 W^T: [l][n][k]
__device__ __align__(16) __half g_H0[(size_t)BROWS * DIM];
__device__ __align__(16) __half g_H1[(size_t)BROWS * DIM];
__device__ __align__(16) __half g_H2[(size_t)BROWS * DIM];
__device__ int   g_route[BROWS];
__device__ float g_minmax[2];
__device__ int   g_ticket;
__device__ int   g_done[4][NBLK]; // per-layer per-row-block tile completion

// ------------------------------- helpers --------------------------------
__device__ __forceinline__ uint32_t smem_u32(const void* p) {
    uint32_t a;
    asm("{ .reg .u64 t; cvta.to.shared.u64 t, %1; cvt.u32.u64 %0, t; }" : "=r"(a) : "l"(p));
    return a;
}
#define CP_ASYNC16(dst, src) \
    asm volatile("cp.async.cg.shared.global [%0], [%1], 16;" :: "r"(dst), "l"(src) : "memory")
#define LDSM_X4(r0, r1, r2, r3, addr) \
    asm volatile("ldmatrix.sync.aligned.m8n8.x4.shared.b16 {%0,%1,%2,%3}, [%4];" \
                 : "=r"(r0), "=r"(r1), "=r"(r2), "=r"(r3) : "r"(addr))

__device__ __forceinline__ float gelu_f(float x) {
    float x3 = x * x * x;
    float t = tanhf(0.7978845608028654f * (x + 0.044715f * x3));
    return 0.5f * x * (1.f + t);
}

// ---------------------------------------------------------------------------
// minmax: exact reduction + scheduler-state reset. One block, 1024 threads.
// ---------------------------------------------------------------------------
__global__ __launch_bounds__(1024)
void minmax_kernel(const float* __restrict__ unc) {
    __shared__ float smin[1024], smax[1024];
    int t = threadIdx.x;
    // reset persistent-scheduler state (graph-replay safe)
    if (t < 4 * NBLK) ((int*)g_done)[t] = 0;
    if (t == 512) g_ticket = 0;

    float mn = FLT_MAX, mx = -FLT_MAX;
    for (int i = t; i < BROWS; i += 1024) {
        float v = unc[i];
        mn = fminf(mn, v); mx = fmaxf(mx, v);
    }
    smin[t] = mn; smax[t] = mx;
    __syncthreads();
    for (int s = 512; s > 0; s >>= 1) {
        if (t < s) {
            smin[t] = fminf(smin[t], smin[t + s]);
            smax[t] = fmaxf(smax[t], smax[t + s]);
        }
        __syncthreads();
    }
    if (t == 0) { g_minmax[0] = smin[0]; g_minmax[1] = smax[0]; }
}

// ---------------------------------------------------------------------------
// router MLP: 32 blocks x 256 threads, one row per thread (parallel!)
// ---------------------------------------------------------------------------
__global__ __launch_bounds__(256)
void route_kernel(const float* __restrict__ unc,
                  const float* __restrict__ rw1, const float* __restrict__ rb1,
                  const float* __restrict__ rw2, const float* __restrict__ rb2,
                  const float* __restrict__ rw3, const float* __restrict__ rb3,
                  float* __restrict__ out_mask) {
    __shared__ float s_w1[32], s_b1[32], s_w2[512], s_b2[16], s_w3[48], s_b3[3];
    int t = threadIdx.x;
    if (t < 32) { s_w1[t] = rw1[t]; s_b1[t] = rb1[t]; }
    for (int i = t; i < 512; i += 256) s_w2[i] = rw2[i];
    if (t < 16) s_b2[t] = rb2[t];
    if (t < 48) s_w3[t] = rw3[t];
    if (t < 3)  s_b3[t] = rb3[t];
    __syncthreads();

    int i = blockIdx.x * 256 + t;
    float mn = g_minmax[0], mx = g_minmax[1];
    float u = (unc[i] - mn) / (mx - mn + 1e-8f);

    float h1[32];
#pragma unroll
    for (int j = 0; j < 32; j++) h1[j] = fmaxf(fmaf(u, s_w1[j], s_b1[j]), 0.f);
    float h2[16];
#pragma unroll
    for (int j = 0; j < 16; j++) {
        float a = s_b2[j];
#pragma unroll
        for (int k = 0; k < 32; k++) a = fmaf(h1[k], s_w2[k * 16 + j], a);
        h2[j] = fmaxf(a, 0.f);
    }
    float l[3];
#pragma unroll
    for (int j = 0; j < 3; j++) {
        float a = s_b3[j];
#pragma unroll
        for (int k = 0; k < 16; k++) a = fmaf(h2[k], s_w3[k * 3 + j], a);
        l[j] = a;
    }
    int r = 0; float best = l[0];
    if (l[1] > best) { best = l[1]; r = 1; }
    if (l[2] > best) { best = l[2]; r = 2; }
    g_route[i]  = r;
    out_mask[i] = (float)r;
}

// ---------------------------------------------------------------------------
// prep: x -> g_X (fp16);  W[l][k][n] -> g_Wt[l][n][k] (fp16)
// ---------------------------------------------------------------------------
__global__ void convx_kernel(const float* __restrict__ x) {
    size_t i = ((size_t)blockIdx.x * 256 + threadIdx.x) * 8;
    float4 v0 = *(const float4*)(x + i);
    float4 v1 = *(const float4*)(x + i + 4);
    uint4 o;
    __half2* ho = (__half2*)&o;
    ho[0] = __floats2half2_rn(v0.x, v0.y);
    ho[1] = __floats2half2_rn(v0.z, v0.w);
    ho[2] = __floats2half2_rn(v1.x, v1.y);
    ho[3] = __floats2half2_rn(v1.z, v1.w);
    *(uint4*)(g_X + i) = o;
}
__global__ void transW_kernel(const float* __restrict__ Ws) {
    __shared__ float tile[32][33];
    int l = blockIdx.z;
    int n0 = blockIdx.x * 32, k0 = blockIdx.y * 32;
    const float* Wl = Ws + (size_t)l * DIM * DIM;
#pragma unroll
    for (int i = 0; i < 4; i++)
        tile[threadIdx.y + i * 8][threadIdx.x] =
            Wl[(size_t)(k0 + threadIdx.y + i * 8) * DIM + n0 + threadIdx.x];
    __syncthreads();
    __half* Wt = g_Wt + (size_t)l * DIM * DIM;
#pragma unroll
    for (int i = 0; i < 4; i++) {
        int n = n0 + threadIdx.y + i * 8;
        Wt[(size_t)n * DIM + k0 + threadIdx.x] =
            __float2half_rn(tile[threadIdx.x][threadIdx.y + i * 8]);
    }
}

// ---------------------------------------------------------------------------
// Persistent FP16 GEMM (R11-proven): all 4 layers, ticket scheduler + dataflow.
// CTA 128x128x64, 8 warps 64x32, 3-stage cp.async, ldmatrix, 2 CTA/SM.
// ---------------------------------------------------------------------------
__global__ __launch_bounds__(NTHREADS, 2)
void gemm_persistent(const float* __restrict__ ball, float* __restrict__ outp) {
    extern __shared__ char smem[];
    __shared__ int s_item;
    uint32_t smem_base = smem_u32(smem);

    int tid  = threadIdx.x;
    int warp = tid >> 5, lane = tid & 31;
    int wm = warp >> 2, wn = warp & 3;
    int gq = lane >> 2, tr = lane & 3;

    int a_row  = ((lane >> 3) & 1) * 8 + (lane & 7);
    int a_colB = (lane >> 4) * 16;
    int b_row  = (lane >> 4) * 8 + (lane & 7);
    int b_colB = ((lane >> 3) & 1) * 16;

    for (;;) {
        if (tid == 0) s_item = atomicAdd(&g_ticket, 1);
        __syncthreads();
        int item = s_item;
        if (item >= TOTAL_TILES) return;

        int layer = item >> 10;
        int rem   = item & 1023;
        int bm = rem >> 4, bn = rem & 15;

        const __half* A; __half* Hptr; int outLevel;
        switch (layer) {
            case 0:  A = g_X;  Hptr = g_H0;    outLevel = 0;  break;
            case 1:  A = g_H0; Hptr = g_H1;    outLevel = 1;  break;
            case 2:  A = g_H1; Hptr = g_H2;    outLevel = -1; break;
            default: A = g_H2; Hptr = nullptr; outLevel = 2;  break;
        }
        const float* bias = ball + layer * DIM;
        const char* aSrc = (const char*)(A + (size_t)bm * BM * DIM);
        const char* bSrc = (const char*)(g_Wt + (size_t)layer * DIM * DIM + (size_t)bn * BN * DIM);

        if (layer > 0) {
            if (tid == 0) {
                volatile int* d = &g_done[layer - 1][bm];
                while (*d < 16) __nanosleep(64);
                __threadfence();
            }
            __syncthreads();
        }

        float acc[4][4][4];
#pragma unroll
        for (int i = 0; i < 4; i++)
#pragma unroll
            for (int j = 0; j < 4; j++)
#pragma unroll
                for (int r = 0; r < 4; r++) acc[i][j][r] = 0.f;

        auto issue = [&](int c) {
            int slot = c % NSTAGE;
            uint32_t ab = smem_base + slot * STAGE_BYTES;
            uint32_t bb = ab + A_SM_BYTES;
            #pragma unroll
            for (int i = 0; i < 4; i++) {
                int g = tid + i * NTHREADS;
                int r = g >> 3, gc = g & 7;
                CP_ASYNC16(ab + (uint32_t)(r * T_STRIDE + gc * 16),
                           aSrc + (size_t)r * (DIM * 2) + (size_t)c * (BK * 2) + gc * 16);
            }
            #pragma unroll
            for (int i = 0; i < 4; i++) {
                int g = tid + i * NTHREADS;
                int r = g >> 3, gc = g & 7;
                CP_ASYNC16(bb + (uint32_t)(r * T_STRIDE + gc * 16),
                           bSrc + (size_t)r * (DIM * 2) + (size_t)c * (BK * 2) + gc * 16);
            }
            asm volatile("cp.async.commit_group;" ::: "memory");
        };

        issue(0);
        issue(1);

        for (int c = 0; c < NCH; c++) {
            if (c < NCH - 1) asm volatile("cp.async.wait_group 1;" ::: "memory");
            else             asm volatile("cp.async.wait_group 0;" ::: "memory");
            __syncthreads();
            if (c + 2 < NCH) issue(c + 2);

            int slot = c % NSTAGE;
            uint32_t aBase = smem_base + slot * STAGE_BYTES
                           + (uint32_t)((wm * 64 + a_row) * T_STRIDE + a_colB);
            uint32_t bBase = smem_base + slot * STAGE_BYTES + A_SM_BYTES
                           + (uint32_t)((wn * 32 + b_row) * T_STRIDE + b_colB);

#pragma unroll
            for (int ks = 0; ks < 4; ks++) {
                uint32_t af[4][4], bf[4][2];
#pragma unroll
                for (int i = 0; i < 4; i++)
                    LDSM_X4(af[i][0], af[i][1], af[i][2], af[i][3],
                            aBase + (uint32_t)(i * 16 * T_STRIDE + ks * 32));
#pragma unroll
                for (int jp = 0; jp < 2; jp++)
                    LDSM_X4(bf[2 * jp][0], bf[2 * jp][1], bf[2 * jp + 1][0], bf[2 * jp + 1][1],
                            bBase + (uint32_t)(jp * 16 * T_STRIDE + ks * 32));
#pragma unroll
                for (int i = 0; i < 4; i++)
#pragma unroll
                    for (int j = 0; j < 4; j++) {
                        asm volatile(
                            "mma.sync.aligned.m16n8k16.row.col.f32.f16.f16.f32 "
                            "{%0,%1,%2,%3}, {%4,%5,%6,%7}, {%8,%9}, {%0,%1,%2,%3};"
                            : "+f"(acc[i][j][0]), "+f"(acc[i][j][1]),
                              "+f"(acc[i][j][2]), "+f"(acc[i][j][3])
                            : "r"(af[i][0]), "r"(af[i][1]), "r"(af[i][2]), "r"(af[i][3]),
                              "r"(bf[j][0]), "r"(bf[j][1]));
                    }
            }
        }

        // ---- epilogue: bias + GELU; H fp16, routed rows -> out (fp32) ----
        int rbase = bm * BM + wm * 64;
        int cbase = bn * BN + wn * 32;
#pragma unroll
        for (int i = 0; i < 4; i++) {
            int row0 = rbase + i * 16 + gq;
            int row1 = row0 + 8;
            int rt0 = g_route[row0], rt1 = g_route[row1];
#pragma unroll
            for (int j = 0; j < 4; j++) {
                int col = cbase + j * 8 + 2 * tr;
                float2 bb = *(const float2*)(bias + col);
                float v00 = gelu_f(acc[i][j][0] + bb.x);
                float v01 = gelu_f(acc[i][j][1] + bb.y);
                float v10 = gelu_f(acc[i][j][2] + bb.x);
                float v11 = gelu_f(acc[i][j][3] + bb.y);
                if (Hptr) {
                    *(__half2*)&Hptr[(size_t)row0 * DIM + col] = __floats2half2_rn(v00, v01);
                    *(__half2*)&Hptr[(size_t)row1 * DIM + col] = __floats2half2_rn(v10, v11);
                }
                if (outLevel >= 0) {
                    if (rt0 == outLevel) *(float2*)&outp[(size_t)row0 * DIM + col] = make_float2(v00, v01);
                    if (rt1 == outLevel) *(float2*)&outp[(size_t)row1 * DIM + col] = make_float2(v10, v11);
                }
            }
        }

        __threadfence();
        __syncthreads();
        if (tid == 0 && layer < 3) atomicAdd(&g_done[layer][bm], 1);
    }
}

// ---------------------------------------------------------------------------
extern "C" void kernel_launch(void* const* d_in, const int* in_sizes, int n_in,
                              void* d_out, int out_size) {
    const float* x   = (const float*)d_in[0];
    const float* unc = (const float*)d_in[1];
    const float* Ws  = (const float*)d_in[2];
    const float* bs  = (const float*)d_in[3];
    const float* rw1 = (const float*)d_in[4];
    const float* rb1 = (const float*)d_in[5];
    const float* rw2 = (const float*)d_in[6];
    const float* rb2 = (const float*)d_in[7];
    const float* rw3 = (const float*)d_in[8];
    const float* rb3 = (const float*)d_in[9];

    float* out  = (float*)d_out;
    float* mask = out + (size_t)BROWS * DIM;

    cudaFuncSetAttribute(gemm_persistent, cudaFuncAttributeMaxDynamicSharedMemorySize, SMEM_TOTAL);

    int sms = 148;
    cudaDeviceGetAttribute(&sms, cudaDevAttrMultiProcessorCount, 0);

    minmax_kernel<<<1, 1024>>>(unc);
    route_kernel<<<32, 256>>>(unc, rw1, rb1, rw2, rb2, rw3, rb3, mask);
    convx_kernel<<<(BROWS * DIM) / (256 * 8), 256>>>(x);
    transW_kernel<<<dim3(64, 64, 4), dim3(32, 8)>>>(Ws);
    gemm_persistent<<<2 * sms, NTHREADS, SMEM_TOTAL>>>(bs, out);
}

// round 16
// speedup vs baseline: 1.4392x; 1.0303x over previous
#include <cuda_runtime.h>
#include <cuda_fp16.h>
#include <cstdint>
#include <cfloat>

#define BROWS 8192
#define DIM   2048
#define NBLK  (BROWS/128)

#define BM 128
#define BN 128
#define BK 64
#define NCH (DIM/BK)              // 32 k-iterations
#define T_STRIDE 144
#define T_SM_BYTES (128*T_STRIDE)       // 18432
#define A_SM_BYTES T_SM_BYTES
#define STAGE_BYTES (2*T_SM_BYTES)      // 36864
#define NSTAGE 3
#define SMEM_TOTAL (NSTAGE*STAGE_BYTES) // 110592

#define NTHREADS 256              // 8 warps, 2x4 grid of 64x32 warp tiles

#define TPL 1024                  // tiles per layer (64 bm x 16 bn)
#define TOTAL_TILES (4*TPL)

// ------------------------- persistent device scratch -------------------------
__device__ __align__(16) __half g_X [(size_t)BROWS * DIM];     // fp16 x
__device__ __align__(16) __half g_Wt[(size_t)4 * DIM * DIM];   // fp16 W^T: [l][n][k]
__device__ __align__(16) __half g_H0[(size_t)BROWS * DIM];
__device__ __align__(16) __half g_H1[(size_t)BROWS * DIM];
__device__ __align__(16) __half g_H2[(size_t)BROWS * DIM];
__device__ int   g_route[BROWS];
__device__ float g_minmax[2];
__device__ int   g_ticket;
__device__ int   g_done[4][NBLK]; // per-layer per-row-block tile completion

// ------------------------------- helpers --------------------------------
__device__ __forceinline__ uint32_t smem_u32(const void* p) {
    uint32_t a;
    asm("{ .reg .u64 t; cvta.to.shared.u64 t, %1; cvt.u32.u64 %0, t; }" : "=r"(a) : "l"(p));
    return a;
}
#define CP_ASYNC16(dst, src) \
    asm volatile("cp.async.cg.shared.global [%0], [%1], 16;" :: "r"(dst), "l"(src) : "memory")
#define LDSM_X4(r0, r1, r2, r3, addr) \
    asm volatile("ldmatrix.sync.aligned.m8n8.x4.shared.b16 {%0,%1,%2,%3}, [%4];" \
                 : "=r"(r0), "=r"(r1), "=r"(r2), "=r"(r3) : "r"(addr))

// HW tanh (sm_75+): single instruction, ~1e-5 rel err — noise vs fp16 rounding
__device__ __forceinline__ float gelu_f(float x) {
    float y = 0.7978845608028654f * fmaf(0.044715f * x * x, x, x);
    float t;
    asm("tanh.approx.f32 %0, %1;" : "=f"(t) : "f"(y));
    return 0.5f * x * (1.f + t);
}

// ---------------------------------------------------------------------------
// minmax: exact reduction + scheduler-state reset. One block, 1024 threads.
// ---------------------------------------------------------------------------
__global__ __launch_bounds__(1024)
void minmax_kernel(const float* __restrict__ unc) {
    __shared__ float smin[1024], smax[1024];
    int t = threadIdx.x;
    if (t < 4 * NBLK) ((int*)g_done)[t] = 0;
    if (t == 512) g_ticket = 0;

    float mn = FLT_MAX, mx = -FLT_MAX;
    for (int i = t; i < BROWS; i += 1024) {
        float v = unc[i];
        mn = fminf(mn, v); mx = fmaxf(mx, v);
    }
    smin[t] = mn; smax[t] = mx;
    __syncthreads();
    for (int s = 512; s > 0; s >>= 1) {
        if (t < s) {
            smin[t] = fminf(smin[t], smin[t + s]);
            smax[t] = fmaxf(smax[t], smax[t + s]);
        }
        __syncthreads();
    }
    if (t == 0) { g_minmax[0] = smin[0]; g_minmax[1] = smax[0]; }
}

// ---------------------------------------------------------------------------
// router MLP: 32 blocks x 256 threads, one row per thread
// ---------------------------------------------------------------------------
__global__ __launch_bounds__(256)
void route_kernel(const float* __restrict__ unc,
                  const float* __restrict__ rw1, const float* __restrict__ rb1,
                  const float* __restrict__ rw2, const float* __restrict__ rb2,
                  const float* __restrict__ rw3, const float* __restrict__ rb3,
                  float* __restrict__ out_mask) {
    __shared__ float s_w1[32], s_b1[32], s_w2[512], s_b2[16], s_w3[48], s_b3[3];
    int t = threadIdx.x;
    if (t < 32) { s_w1[t] = rw1[t]; s_b1[t] = rb1[t]; }
    for (int i = t; i < 512; i += 256) s_w2[i] = rw2[i];
    if (t < 16) s_b2[t] = rb2[t];
    if (t < 48) s_w3[t] = rw3[t];
    if (t < 3)  s_b3[t] = rb3[t];
    __syncthreads();

    int i = blockIdx.x * 256 + t;
    float mn = g_minmax[0], mx = g_minmax[1];
    float u = (unc[i] - mn) / (mx - mn + 1e-8f);

    float h1[32];
#pragma unroll
    for (int j = 0; j < 32; j++) h1[j] = fmaxf(fmaf(u, s_w1[j], s_b1[j]), 0.f);
    float h2[16];
#pragma unroll
    for (int j = 0; j < 16; j++) {
        float a = s_b2[j];
#pragma unroll
        for (int k = 0; k < 32; k++) a = fmaf(h1[k], s_w2[k * 16 + j], a);
        h2[j] = fmaxf(a, 0.f);
    }
    float l[3];
#pragma unroll
    for (int j = 0; j < 3; j++) {
        float a = s_b3[j];
#pragma unroll
        for (int k = 0; k < 16; k++) a = fmaf(h2[k], s_w3[k * 3 + j], a);
        l[j] = a;
    }
    int r = 0; float best = l[0];
    if (l[1] > best) { best = l[1]; r = 1; }
    if (l[2] > best) { best = l[2]; r = 2; }
    g_route[i]  = r;
    out_mask[i] = (float)r;
}

// ---------------------------------------------------------------------------
// prep: x -> g_X (fp16);  W[l][k][n] -> g_Wt[l][n][k] (fp16)
// ---------------------------------------------------------------------------
__global__ void convx_kernel(const float* __restrict__ x) {
    size_t i = ((size_t)blockIdx.x * 256 + threadIdx.x) * 8;
    float4 v0 = *(const float4*)(x + i);
    float4 v1 = *(const float4*)(x + i + 4);
    uint4 o;
    __half2* ho = (__half2*)&o;
    ho[0] = __floats2half2_rn(v0.x, v0.y);
    ho[1] = __floats2half2_rn(v0.z, v0.w);
    ho[2] = __floats2half2_rn(v1.x, v1.y);
    ho[3] = __floats2half2_rn(v1.z, v1.w);
    *(uint4*)(g_X + i) = o;
}
__global__ void transW_kernel(const float* __restrict__ Ws) {
    __shared__ float tile[32][33];
    int l = blockIdx.z;
    int n0 = blockIdx.x * 32, k0 = blockIdx.y * 32;
    const float* Wl = Ws + (size_t)l * DIM * DIM;
#pragma unroll
    for (int i = 0; i < 4; i++)
        tile[threadIdx.y + i * 8][threadIdx.x] =
            Wl[(size_t)(k0 + threadIdx.y + i * 8) * DIM + n0 + threadIdx.x];
    __syncthreads();
    __half* Wt = g_Wt + (size_t)l * DIM * DIM;
#pragma unroll
    for (int i = 0; i < 4; i++) {
        int n = n0 + threadIdx.y + i * 8;
        Wt[(size_t)n * DIM + k0 + threadIdx.x] =
            __float2half_rn(tile[threadIdx.x][threadIdx.y + i * 8]);
    }
}

// ---------------------------------------------------------------------------
// Persistent FP16 GEMM: all 4 layers, ticket scheduler + dataflow sync.
// CTA 128x128x64, 8 warps 64x32, 3-stage cp.async, ldmatrix, 2 CTA/SM.
// ---------------------------------------------------------------------------
__global__ __launch_bounds__(NTHREADS, 2)
void gemm_persistent(const float* __restrict__ ball, float* __restrict__ outp) {
    extern __shared__ char smem[];
    __shared__ int s_item;
    uint32_t smem_base = smem_u32(smem);

    int tid  = threadIdx.x;
    int warp = tid >> 5, lane = tid & 31;
    int wm = warp >> 2, wn = warp & 3;
    int gq = lane >> 2, tr = lane & 3;

    int a_row  = ((lane >> 3) & 1) * 8 + (lane & 7);
    int a_colB = (lane >> 4) * 16;
    int b_row  = (lane >> 4) * 8 + (lane & 7);
    int b_colB = ((lane >> 3) & 1) * 16;

    for (;;) {
        if (tid == 0) s_item = atomicAdd(&g_ticket, 1);
        __syncthreads();
        int item = s_item;
        if (item >= TOTAL_TILES) return;

        int layer = item >> 10;
        int rem   = item & 1023;
        int bm = rem >> 4, bn = rem & 15;

        const __half* A; __half* Hptr; int outLevel;
        switch (layer) {
            case 0:  A = g_X;  Hptr = g_H0;    outLevel = 0;  break;
            case 1:  A = g_H0; Hptr = g_H1;    outLevel = 1;  break;
            case 2:  A = g_H1; Hptr = g_H2;    outLevel = -1; break;
            default: A = g_H2; Hptr = nullptr; outLevel = 2;  break;
        }
        const float* bias = ball + layer * DIM;
        const char* aSrc = (const char*)(A + (size_t)bm * BM * DIM);
        const char* bSrc = (const char*)(g_Wt + (size_t)layer * DIM * DIM + (size_t)bn * BN * DIM);

        if (layer > 0) {
            if (tid == 0) {
                volatile int* d = &g_done[layer - 1][bm];
                while (*d < 16) __nanosleep(64);
                __threadfence();
            }
            __syncthreads();
        }

        float acc[4][4][4];
#pragma unroll
        for (int i = 0; i < 4; i++)
#pragma unroll
            for (int j = 0; j < 4; j++)
#pragma unroll
                for (int r = 0; r < 4; r++) acc[i][j][r] = 0.f;

        auto issue = [&](int c) {
            int slot = c % NSTAGE;
            uint32_t ab = smem_base + slot * STAGE_BYTES;
            uint32_t bb = ab + A_SM_BYTES;
            #pragma unroll
            for (int i = 0; i < 4; i++) {
                int g = tid + i * NTHREADS;
                int r = g >> 3, gc = g & 7;
                CP_ASYNC16(ab + (uint32_t)(r * T_STRIDE + gc * 16),
                           aSrc + (size_t)r * (DIM * 2) + (size_t)c * (BK * 2) + gc * 16);
            }
            #pragma unroll
            for (int i = 0; i < 4; i++) {
                int g = tid + i * NTHREADS;
                int r = g >> 3, gc = g & 7;
                CP_ASYNC16(bb + (uint32_t)(r * T_STRIDE + gc * 16),
                           bSrc + (size_t)r * (DIM * 2) + (size_t)c * (BK * 2) + gc * 16);
            }
            asm volatile("cp.async.commit_group;" ::: "memory");
        };

        issue(0);
        issue(1);

        for (int c = 0; c < NCH; c++) {
            if (c < NCH - 1) asm volatile("cp.async.wait_group 1;" ::: "memory");
            else             asm volatile("cp.async.wait_group 0;" ::: "memory");
            __syncthreads();
            if (c + 2 < NCH) issue(c + 2);

            int slot = c % NSTAGE;
            uint32_t aBase = smem_base + slot * STAGE_BYTES
                           + (uint32_t)((wm * 64 + a_row) * T_STRIDE + a_colB);
            uint32_t bBase = smem_base + slot * STAGE_BYTES + A_SM_BYTES
                           + (uint32_t)((wn * 32 + b_row) * T_STRIDE + b_colB);

#pragma unroll
            for (int ks = 0; ks < 4; ks++) {
                uint32_t af[4][4], bf[4][2];
#pragma unroll
                for (int i = 0; i < 4; i++)
                    LDSM_X4(af[i][0], af[i][1], af[i][2], af[i][3],
                            aBase + (uint32_t)(i * 16 * T_STRIDE + ks * 32));
#pragma unroll
                for (int jp = 0; jp < 2; jp++)
                    LDSM_X4(bf[2 * jp][0], bf[2 * jp][1], bf[2 * jp + 1][0], bf[2 * jp + 1][1],
                            bBase + (uint32_t)(jp * 16 * T_STRIDE + ks * 32));
#pragma unroll
                for (int i = 0; i < 4; i++)
#pragma unroll
                    for (int j = 0; j < 4; j++) {
                        asm volatile(
                            "mma.sync.aligned.m16n8k16.row.col.f32.f16.f16.f32 "
                            "{%0,%1,%2,%3}, {%4,%5,%6,%7}, {%8,%9}, {%0,%1,%2,%3};"
                            : "+f"(acc[i][j][0]), "+f"(acc[i][j][1]),
                              "+f"(acc[i][j][2]), "+f"(acc[i][j][3])
                            : "r"(af[i][0]), "r"(af[i][1]), "r"(af[i][2]), "r"(af[i][3]),
                              "r"(bf[j][0]), "r"(bf[j][1]));
                    }
            }
        }

        // ---- epilogue: bias + GELU; H fp16, routed rows -> out (fp32) ----
        int rbase = bm * BM + wm * 64;
        int cbase = bn * BN + wn * 32;
#pragma unroll
        for (int i = 0; i < 4; i++) {
            int row0 = rbase + i * 16 + gq;
            int row1 = row0 + 8;
            int rt0 = (outLevel >= 0) ? g_route[row0] : -1;
            int rt1 = (outLevel >= 0) ? g_route[row1] : -1;
#pragma unroll
            for (int j = 0; j < 4; j++) {
                int col = cbase + j * 8 + 2 * tr;
                float2 bb = *(const float2*)(bias + col);
                float v00 = gelu_f(acc[i][j][0] + bb.x);
                float v01 = gelu_f(acc[i][j][1] + bb.y);
                float v10 = gelu_f(acc[i][j][2] + bb.x);
                float v11 = gelu_f(acc[i][j][3] + bb.y);
                if (Hptr) {
                    *(__half2*)&Hptr[(size_t)row0 * DIM + col] = __floats2half2_rn(v00, v01);
                    *(__half2*)&Hptr[(size_t)row1 * DIM + col] = __floats2half2_rn(v10, v11);
                }
                if (outLevel >= 0) {
                    if (rt0 == outLevel) *(float2*)&outp[(size_t)row0 * DIM + col] = make_float2(v00, v01);
                    if (rt1 == outLevel) *(float2*)&outp[(size_t)row1 * DIM + col] = make_float2(v10, v11);
                }
            }
        }

        // publish completion only when there are consumers (layers 0-2)
        if (layer < 3) {
            __threadfence();
            __syncthreads();
            if (tid == 0) atomicAdd(&g_done[layer][bm], 1);
        }
    }
}

// ---------------------------------------------------------------------------
extern "C" void kernel_launch(void* const* d_in, const int* in_sizes, int n_in,
                              void* d_out, int out_size) {
    const float* x   = (const float*)d_in[0];
    const float* unc = (const float*)d_in[1];
    const float* Ws  = (const float*)d_in[2];
    const float* bs  = (const float*)d_in[3];
    const float* rw1 = (const float*)d_in[4];
    const float* rb1 = (const float*)d_in[5];
    const float* rw2 = (const float*)d_in[6];
    const float* rb2 = (const float*)d_in[7];
    const float* rw3 = (const float*)d_in[8];
    const float* rb3 = (const float*)d_in[9];

    float* out  = (float*)d_out;
    float* mask = out + (size_t)BROWS * DIM;

    cudaFuncSetAttribute(gemm_persistent, cudaFuncAttributeMaxDynamicSharedMemorySize, SMEM_TOTAL);

    int sms = 148;
    cudaDeviceGetAttribute(&sms, cudaDevAttrMultiProcessorCount, 0);

    minmax_kernel<<<1, 1024>>>(unc);
    route_kernel<<<32, 256>>>(unc, rw1, rb1, rw2, rb2, rw3, rb3, mask);
    convx_kernel<<<(BROWS * DIM) / (256 * 8), 256>>>(x);
    transW_kernel<<<dim3(64, 64, 4), dim3(32, 8)>>>(Ws);
    gemm_persistent<<<2 * sms, NTHREADS, SMEM_TOTAL>>>(bs, out);
}